// round 2
// baseline (speedup 1.0000x reference)
#include <cuda_runtime.h>
#include <cuda_bf16.h>
#include <cstdint>

// ---------------------------------------------------------------------------
// GatingNetwork: logits = x @ W^T + b ; softmax ; top-2 (values, indices)
// x: [16384, 4096] f32, W: [64, 4096] f32, b: [64] f32
// out: [0..32768) = top2 values row-major, [32768..65536) = indices as float
//
// mma.sync m16n8k16 bf16 (HMMA), 3-way bf16 split of both operands, 6 partial
// products -> ~fp32 accuracy. W pre-split + fragment-packed by prep kernel,
// streamed via cp.async (3-buffer ring). x converted in registers, depth-3
// software pipeline. A-operand = W (M=64 experts), B = tokens.
// ---------------------------------------------------------------------------

#define HIDDEN   4096
#define NEXP     64
#define NTOK     16384
#define MTILE    128
#define NCTA     (NTOK / MTILE)        // 128
#define THREADS  256
#define NSTEP    (HIDDEN / 16)         // 256 k16-steps
#define STEPS_PER_CHUNK 8              // K=128 per W chunk
#define NCHUNK   (NSTEP / STEPS_PER_CHUNK)  // 32

// W fragment image: per k16 step: 4 mblocks x 3 splits x 32 lanes x uint4
#define FRAG_PER_STEP   (4 * 3 * 32)           // uint4 count = 384
#define CHUNK_BYTES     (STEPS_PER_CHUNK * FRAG_PER_STEP * 16)  // 49152
#define SMEM_TOTAL      (3 * CHUNK_BYTES)      // 147456

__device__ uint4 g_Wfrag[NSTEP * FRAG_PER_STEP];   // 1.5 MB

static __device__ __forceinline__ uint32_t s2u(const void* p) {
    uint32_t a;
    asm("{ .reg .u64 t; cvta.to.shared.u64 t, %1; cvt.u32.u64 %0, t; }" : "=r"(a) : "l"(p));
    return a;
}

// pack bf16x2: hi = bf16(f_odd), lo = bf16(f_even)
static __device__ __forceinline__ uint32_t pack2(float f_even, float f_odd) {
    uint32_t r;
    asm("cvt.rn.bf16x2.f32 %0, %1, %2;" : "=r"(r) : "f"(f_odd), "f"(f_even));
    return r;
}

#define MMA(D, A0, A1, A2, A3, B0, B1)                                        \
    asm volatile(                                                             \
        "mma.sync.aligned.m16n8k16.row.col.f32.bf16.bf16.f32 "                \
        "{%0,%1,%2,%3},{%4,%5,%6,%7},{%8,%9},{%0,%1,%2,%3};"                  \
        : "+f"((D)[0]), "+f"((D)[1]), "+f"((D)[2]), "+f"((D)[3])              \
        : "r"(A0), "r"(A1), "r"(A2), "r"(A3), "r"(B0), "r"(B1))

#define LDS128(A0, A1, A2, A3, addr)                                          \
    asm volatile("ld.shared.v4.b32 {%0,%1,%2,%3}, [%4];"                      \
                 : "=r"(A0), "=r"(A1), "=r"(A2), "=r"(A3) : "r"(addr))

static __device__ __forceinline__ void cp16(uint32_t sdst, const void* gsrc) {
    asm volatile("cp.async.cg.shared.global [%0], [%1], 16;"
                 :: "r"(sdst), "l"(gsrc) : "memory");
}

// ---------------------------------------------------------------------------
// Prep: split W into bf16 hi/mid/lo and pack into mma A-fragment order.
// Layout index: ((t*4 + mb)*3 + s)*32 + lane, one uint4 each:
//   {a0a1, a2a3, a4a5, a6a7} for A tile rows = experts mb*16.., cols = k.
// ---------------------------------------------------------------------------
static __device__ __forceinline__ float split_res(float f, int s) {
    // residual after s bf16 peel-offs
    for (int i = 0; i < s; i++)
        f -= __bfloat162float(__float2bfloat16_rn(f));
    return f;
}

__global__ void prep_w_kernel(const float* __restrict__ W) {
    int idx = blockIdx.x * blockDim.x + threadIdx.x;
    if (idx >= NSTEP * FRAG_PER_STEP) return;
    int l = idx & 31;
    int r = idx >> 5;
    int s = r % 3;  r /= 3;
    int mb = r & 3;
    int t = r >> 2;

    int q = l & 3;
    int row0 = mb * 16 + (l >> 2);
    int row1 = row0 + 8;
    int c = t * 16 + 2 * q;

    const float* w0 = W + (size_t)row0 * HIDDEN + c;
    const float* w1 = W + (size_t)row1 * HIDDEN + c;

    float f00 = split_res(w0[0], s), f01 = split_res(w0[1], s);
    float f10 = split_res(w1[0], s), f11 = split_res(w1[1], s);
    float f02 = split_res(w0[8], s), f03 = split_res(w0[9], s);
    float f12 = split_res(w1[8], s), f13 = split_res(w1[9], s);

    uint4 v;
    v.x = pack2(f00, f01);   // a0,a1: row0, k, k+1
    v.y = pack2(f10, f11);   // a2,a3: row1
    v.z = pack2(f02, f03);   // a4,a5: row0, k+8
    v.w = pack2(f12, f13);   // a6,a7: row1, k+8
    g_Wfrag[idx] = v;
}

// ---------------------------------------------------------------------------
// Main kernel
// ---------------------------------------------------------------------------
__global__ __launch_bounds__(THREADS, 1)
void gating_kernel(const float* __restrict__ x,
                   const float* __restrict__ bias,
                   float* __restrict__ out) {
    extern __shared__ char smem[];
    const uint32_t sb = s2u(smem);
    const int tid = threadIdx.x;
    const int w   = tid >> 5;
    const int l   = tid & 31;
    const int q   = l & 3;

    // ---- W chunk copier (cp.async ring of 3) ----
    auto issue_chunk = [&](int ch) {
        const char* gsrc = (const char*)g_Wfrag + (size_t)ch * CHUNK_BYTES;
        uint32_t sdst = sb + (ch % 3) * CHUNK_BYTES;
#pragma unroll
        for (int i = 0; i < CHUNK_BYTES / 16 / THREADS; i++) {
            int off = (tid + i * THREADS) * 16;
            cp16(sdst + off, gsrc + off);
        }
        asm volatile("cp.async.commit_group;" ::: "memory");
    };

    issue_chunk(0);
    issue_chunk(1);

    // ---- x pointers: token = tbase + l/4 (g adds 8); k offset = 2q (+8) ----
    const int tbase = blockIdx.x * MTILE + w * 16;
    const float* p0 = x + (size_t)(tbase + (l >> 2)) * HIDDEN + 2 * q;
    const float* p1 = p0 + (size_t)8 * HIDDEN;

    // x software pipeline: [slot][g][half] float2
    float2 vx[3][2][2];
#pragma unroll
    for (int d = 0; d < 3; d++) {
        vx[d][0][0] = *(const float2*)(p0 + d * 16);
        vx[d][0][1] = *(const float2*)(p0 + d * 16 + 8);
        vx[d][1][0] = *(const float2*)(p1 + d * 16);
        vx[d][1][1] = *(const float2*)(p1 + d * 16 + 8);
    }

    float D[4][2][4];
#pragma unroll
    for (int mb = 0; mb < 4; mb++)
#pragma unroll
        for (int g = 0; g < 2; g++)
#pragma unroll
            for (int i = 0; i < 4; i++) D[mb][g][i] = 0.0f;

#pragma unroll 1
    for (int t = 0; t < NSTEP; t++) {
        if ((t & (STEPS_PER_CHUNK - 1)) == 0) {
            const int ch = t / STEPS_PER_CHUNK;
            if (ch < NCHUNK - 1)
                asm volatile("cp.async.wait_group 1;" ::: "memory");
            else
                asm volatile("cp.async.wait_group 0;" ::: "memory");
            __syncthreads();
            if (ch + 2 < NCHUNK) issue_chunk(ch + 2);
        }

        const int slot = t % 3;

        // ---- build B fragments: Bs[split][g][half] ----
        uint32_t Bs[3][2][2];
#pragma unroll
        for (int g = 0; g < 2; g++) {
#pragma unroll
            for (int h = 0; h < 2; h++) {
                float f0 = vx[slot][g][h].x, f1 = vx[slot][g][h].y;
                uint32_t H = pack2(f0, f1);
                float h0 = __uint_as_float(H << 16);
                float h1 = __uint_as_float(H & 0xFFFF0000u);
                float m0 = f0 - h0, m1 = f1 - h1;
                uint32_t M = pack2(m0, m1);
                float mm0 = __uint_as_float(M << 16);
                float mm1 = __uint_as_float(M & 0xFFFF0000u);
                uint32_t L = pack2(m0 - mm0, m1 - mm1);
                Bs[0][g][h] = H; Bs[1][g][h] = M; Bs[2][g][h] = L;
            }
        }

        // ---- prefetch x for step t+3 into this slot ----
        if (t + 3 < NSTEP) {
            const float* q0 = p0 + (size_t)(t + 3) * 16;
            const float* q1 = p1 + (size_t)(t + 3) * 16;
            vx[slot][0][0] = *(const float2*)(q0);
            vx[slot][0][1] = *(const float2*)(q0 + 8);
            vx[slot][1][0] = *(const float2*)(q1);
            vx[slot][1][1] = *(const float2*)(q1 + 8);
        }

        // ---- 48 HMMA: 4 mblocks x {HxH,HxM,HxL, MxH,MxM, LxH} x 2 groups ----
        const uint32_t base = sb + ((t / STEPS_PER_CHUNK) % 3) * CHUNK_BYTES
                              + (t & (STEPS_PER_CHUNK - 1)) * (FRAG_PER_STEP * 16)
                              + l * 16;
#pragma unroll
        for (int mb = 0; mb < 4; mb++) {
            uint32_t A0, A1, A2, A3;
            const uint32_t mbase = base + mb * 3 * 512;
            // A split H
            LDS128(A0, A1, A2, A3, mbase);
            MMA(D[mb][0], A0, A1, A2, A3, Bs[0][0][0], Bs[0][0][1]);
            MMA(D[mb][1], A0, A1, A2, A3, Bs[0][1][0], Bs[0][1][1]);
            MMA(D[mb][0], A0, A1, A2, A3, Bs[1][0][0], Bs[1][0][1]);
            MMA(D[mb][1], A0, A1, A2, A3, Bs[1][1][0], Bs[1][1][1]);
            MMA(D[mb][0], A0, A1, A2, A3, Bs[2][0][0], Bs[2][0][1]);
            MMA(D[mb][1], A0, A1, A2, A3, Bs[2][1][0], Bs[2][1][1]);
            // A split M
            LDS128(A0, A1, A2, A3, mbase + 512);
            MMA(D[mb][0], A0, A1, A2, A3, Bs[0][0][0], Bs[0][0][1]);
            MMA(D[mb][1], A0, A1, A2, A3, Bs[0][1][0], Bs[0][1][1]);
            MMA(D[mb][0], A0, A1, A2, A3, Bs[1][0][0], Bs[1][0][1]);
            MMA(D[mb][1], A0, A1, A2, A3, Bs[1][1][0], Bs[1][1][1]);
            // A split L
            LDS128(A0, A1, A2, A3, mbase + 1024);
            MMA(D[mb][0], A0, A1, A2, A3, Bs[0][0][0], Bs[0][0][1]);
            MMA(D[mb][1], A0, A1, A2, A3, Bs[0][1][0], Bs[0][1][1]);
        }
    }

    // ---- epilogue: stage logits in smem (reuse buffer 0 region) ----
    // All cp.async complete (wait_group 0 at last chunk). Warps only read
    // buf (31%3)=2 and buf 1 after the last sync; slog uses bytes [0, 33280).
    float* slog = (float*)smem;   // pitch 65 floats per token
#pragma unroll
    for (int mb = 0; mb < 4; mb++) {
        int e0 = mb * 16 + (l >> 2);
        int e1 = e0 + 8;
#pragma unroll
        for (int g = 0; g < 2; g++) {
            int tk = w * 16 + g * 8 + 2 * q;   // local token
            slog[(size_t)tk * 65 + e0]       = D[mb][g][0];
            slog[(size_t)(tk + 1) * 65 + e0] = D[mb][g][1];
            slog[(size_t)tk * 65 + e1]       = D[mb][g][2];
            slog[(size_t)(tk + 1) * 65 + e1] = D[mb][g][3];
        }
    }
    __syncthreads();

    if (tid < MTILE) {
        const float* row = slog + (size_t)tid * 65;
        float m1 = -3.4e38f, m2 = -3.4e38f;
        int i1 = 0, i2 = 0;
        float lg[NEXP];
#pragma unroll
        for (int e = 0; e < NEXP; e++) {
            float vv = row[e] + bias[e];
            lg[e] = vv;
            if (vv > m1) { m2 = m1; i2 = i1; m1 = vv; i1 = e; }
            else if (vv > m2) { m2 = vv; i2 = e; }
        }
        float s = 0.0f;
#pragma unroll
        for (int e = 0; e < NEXP; e++) s += __expf(lg[e] - m1);

        const float v1 = 1.0f / s;
        const float v2 = __expf(m2 - m1) * v1;
        const int token = blockIdx.x * MTILE + tid;
        ((float2*)out)[token] = make_float2(v1, v2);
        ((float2*)(out + 2 * NTOK))[token] = make_float2((float)i1, (float)i2);
    }
}

// ---------------------------------------------------------------------------
extern "C" void kernel_launch(void* const* d_in, const int* in_sizes, int n_in,
                              void* d_out, int out_size) {
    const float* x = (const float*)d_in[0];
    const float* W = (const float*)d_in[1];
    const float* b = (const float*)d_in[2];
    float* out = (float*)d_out;

    cudaFuncSetAttribute(gating_kernel, cudaFuncAttributeMaxDynamicSharedMemorySize,
                         SMEM_TOTAL);

    prep_w_kernel<<<(NSTEP * FRAG_PER_STEP + 255) / 256, 256>>>(W);
    gating_kernel<<<NCTA, THREADS, SMEM_TOTAL>>>(x, b, out);
}